// round 13
// baseline (speedup 1.0000x reference)
#include <cuda_runtime.h>
#include <cuda_fp16.h>

// Fisher-Kolmogorov rollout. R13 = R12 with z-tile 16: block (32,8,2), each
// thread computes 8 z-points via 4 register-shifted z-pair sub-iterations.
// Tile y=8,z=16 -> halo 1.40625x (46.5 MB/step); grid 256 CTAs = 1 wave.

#define W        128
#define BATCH    2
#define SUBSTEPS 10
#define MAX_DAYS 4
#define NSTEPS   (SUBSTEPS * MAX_DAYS)
#define MICRO_DT 0.1f

#define VOL  ((size_t)W * W * W)
#define NTOT (BATCH * VOL)

__device__ float g_buf0[NTOT];
__device__ float g_buf1[NTOT];
__device__ __half2 g_dr[NTOT];          // {D, rho} per point (16 MB)

struct __align__(16) H24 { __half2 h[4]; };

__device__ __forceinline__ float4 f4ld(const float* p) {
    return *reinterpret_cast<const float4*>(p);
}

__device__ __forceinline__ void fk_comp(float& o, float c, float nb2,
                                        float nb4, __half2 drh)
{
    const float2 d2 = __half22float2(drh);        // x=D, y=rho
    const float lap = nb2 + nb4 - 6.0f * c;
    o = c + MICRO_DT * (d2.x * lap + d2.y * c * (1.0f - c));
}

__device__ __forceinline__ float4 fk_point(float4 c, float4 ym, float4 yp,
                                           float4 zm, float4 zp,
                                           float lf, float rt, H24 q)
{
    float4 o;
    fk_comp(o.x, c.x, lf  + c.y, ym.x + yp.x + zm.x + zp.x, q.h[0]);
    fk_comp(o.y, c.y, c.x + c.z, ym.y + yp.y + zm.y + zp.y, q.h[1]);
    fk_comp(o.z, c.z, c.y + c.w, ym.z + yp.z + zm.z + zp.z, q.h[2]);
    fk_comp(o.w, c.w, c.z + rt,  ym.w + yp.w + zm.w + zp.w, q.h[3]);
    return o;
}

__device__ __forceinline__ float4 clip01(float4 v)
{
    v.x = fminf(fmaxf(v.x, 0.f), 1.f);
    v.y = fminf(fmaxf(v.y, 0.f), 1.f);
    v.z = fminf(fmaxf(v.z, 0.f), 1.f);
    v.w = fminf(fmaxf(v.w, 0.f), 1.f);
    return v;
}

__device__ __forceinline__ H24 pack_dr(float4 d, float4 r)
{
    H24 q;
    q.h[0] = __floats2half2_rn(d.x, r.x);
    q.h[1] = __floats2half2_rn(d.y, r.y);
    q.h[2] = __floats2half2_rn(d.z, r.z);
    q.h[3] = __floats2half2_rn(d.w, r.w);
    return q;
}

__device__ __forceinline__ void xhalo(float4 u, int tx, float& lf, float& rt)
{
    lf = __shfl_up_sync(0xffffffffu, u.w, 1);
    rt = __shfl_down_sync(0xffffffffu, u.x, 1);
    if (tx == 0)  lf = 0.f;
    if (tx == 31) rt = 0.f;
}

// ---- step 0 (R9 geometry): fp32 in, pack g_dr, micro-step 0 ----
__global__ __launch_bounds__(512)
void fk_step0(const float* __restrict__ usrc,
              float* __restrict__ udst,
              const float* __restrict__ Dm,
              const float* __restrict__ Rm,
              __half2* __restrict__ dr,
              const int* __restrict__ dt_days)
{
#if __CUDA_ARCH__ >= 900
    cudaTriggerProgrammaticLaunchCompletion();
#endif
    const int b  = blockIdx.z;
    const int dt = __ldg(dt_days + b);
    if (dt <= 0) return;                 // step 0 (day 0) is never "fin"

    const int tx = threadIdx.x;
    const int y  = blockIdx.y * 4 + threadIdx.y;
    const int z0 = (blockIdx.x * 4 + threadIdx.z) * 2;
    const int x4 = tx << 2;

    const size_t PL = (size_t)W * W;
    const size_t base = ((size_t)b * VOL) + (((size_t)z0 * W) + y) * W + x4;

    const float4 zero4 = make_float4(0.f, 0.f, 0.f, 0.f);

    const float4 um  = (z0 > 0)     ? f4ld(usrc + base - PL)     : zero4;
    const float4 u0  =                f4ld(usrc + base);
    const float4 u1  =                f4ld(usrc + base + PL);
    const float4 up  = (z0 < W - 2) ? f4ld(usrc + base + 2 * PL) : zero4;
    const float4 ym0 = (y > 0)      ? f4ld(usrc + base - W)      : zero4;
    const float4 yp0 = (y < W - 1)  ? f4ld(usrc + base + W)      : zero4;
    const float4 ym1 = (y > 0)      ? f4ld(usrc + base + PL - W) : zero4;
    const float4 yp1 = (y < W - 1)  ? f4ld(usrc + base + PL + W) : zero4;
    const float4 d0  = f4ld(Dm + base);
    const float4 r0  = f4ld(Rm + base);
    const float4 d1  = f4ld(Dm + base + PL);
    const float4 r1  = f4ld(Rm + base + PL);

    const H24 q0 = pack_dr(d0, r0);
    const H24 q1 = pack_dr(d1, r1);
    *reinterpret_cast<H24*>(dr + base)      = q0;
    *reinterpret_cast<H24*>(dr + base + PL) = q1;

    float lf0, rt0, lf1, rt1;
    xhalo(u0, tx, lf0, rt0);
    xhalo(u1, tx, lf1, rt1);

    const float4 o0 = fk_point(u0, ym0, yp0, um, u1, lf0, rt0, q0);
    const float4 o1 = fk_point(u1, ym1, yp1, u0, up, lf1, rt1, q1);

    *reinterpret_cast<float4*>(udst + base)      = o0;
    *reinterpret_cast<float4*>(udst + base + PL) = o1;
}

// ---- steps 1..39: block (32,8,2); 8 z/thread = 4 z-pair sub-iterations ----
__global__ __launch_bounds__(512, 2)
void fk_step(const float* __restrict__ usrc,
             float* __restrict__ udst,
             float* __restrict__ uout,
             const __half2* __restrict__ dr,
             const int* __restrict__ dt_days,
             int day, int sub)
{
#if __CUDA_ARCH__ >= 900
    cudaTriggerProgrammaticLaunchCompletion();
#endif
    const int b  = blockIdx.z;
    const int dt = __ldg(dt_days + b);   // never written by any kernel
    if (day >= dt) return;                // inactive: fully overlapped via PDL
    const bool fin = (day == dt - 1) && (sub == SUBSTEPS - 1);

    const int tx = threadIdx.x;
    const int y  = blockIdx.y * 8 + threadIdx.y;        // tile y = 8
    const int zb = blockIdx.x * 16 + threadIdx.z * 8;   // tile z = 16; 8 z/thread
    const int x4 = tx << 2;

    const size_t PL = (size_t)W * W;
    size_t base = ((size_t)b * VOL) + (((size_t)zb * W) + y) * W + x4;

#if __CUDA_ARCH__ >= 900
    cudaGridDependencySynchronize();
#endif

    const float4 zero4 = make_float4(0.f, 0.f, 0.f, 0.f);
    const bool ylo = (y > 0), yhi = (y < W - 1);

    // register-carried z planes: um = plane(z-1), u0 = plane(z)
    float4 um = (zb > 0) ? f4ld(usrc + base - PL) : zero4;
    float4 u0 = f4ld(usrc + base);

    #pragma unroll
    for (int k = 0; k < 4; ++k) {
        // outputs z = zb+2k, zb+2k+1 ; planes needed: um,u0 (carried), u1,u2
        const int zp2 = zb + 2 * k + 2;                 // <= zb+8 <= 128
        const float4 u1 = f4ld(usrc + base + PL);
        const float4 u2 = (zp2 < W) ? f4ld(usrc + base + 2 * PL) : zero4;
        const float4 ym0 = ylo ? f4ld(usrc + base - W)      : zero4;
        const float4 yp0 = yhi ? f4ld(usrc + base + W)      : zero4;
        const float4 ym1 = ylo ? f4ld(usrc + base + PL - W) : zero4;
        const float4 yp1 = yhi ? f4ld(usrc + base + PL + W) : zero4;
        const H24 q0 = *reinterpret_cast<const H24*>(dr + base);
        const H24 q1 = *reinterpret_cast<const H24*>(dr + base + PL);

        float lf0, rt0, lf1, rt1;
        xhalo(u0, tx, lf0, rt0);
        xhalo(u1, tx, lf1, rt1);

        float4 o0 = fk_point(u0, ym0, yp0, um, u1, lf0, rt0, q0);
        float4 o1 = fk_point(u1, ym1, yp1, u0, u2, lf1, rt1, q1);

        if (fin) {
            *reinterpret_cast<float4*>(uout + base)      = clip01(o0);
            *reinterpret_cast<float4*>(uout + base + PL) = clip01(o1);
        } else {
            *reinterpret_cast<float4*>(udst + base)      = o0;
            *reinterpret_cast<float4*>(udst + base + PL) = o1;
        }

        um = u1; u0 = u2;                 // shift planes for next pair
        base += 2 * PL;
    }
}

// dt==0 batches: clipped copy of u_t0 -> d_out (independent; no gridsync).
__global__ __launch_bounds__(512)
void fk_tail(const float* __restrict__ u0,
             float* __restrict__ out,
             const int* __restrict__ dt_days)
{
#if __CUDA_ARCH__ >= 900
    cudaTriggerProgrammaticLaunchCompletion();
#endif
    const int b = blockIdx.z >> 5;
    if (__ldg(dt_days + b) != 0) return;

    const int x4 = threadIdx.x << 2;
    const int y  = blockIdx.y * 4 + threadIdx.y;
    const int z  = (blockIdx.z & 31) * 4 + threadIdx.z;
    const size_t base = (((size_t)b * W + z) * W + y) * W + x4;

    float4 v = f4ld(u0 + base);
    *reinterpret_cast<float4*>(out + base) = clip01(v);
}

extern "C" void kernel_launch(void* const* d_in, const int* in_sizes, int n_in,
                              void* d_out, int out_size)
{
    const float* u_t0    = (const float*)d_in[0];
    const float* D_map   = (const float*)d_in[1];
    const float* rho_map = (const float*)d_in[2];
    const int*   dt_days = (const int*)  d_in[3];
    float*       out     = (float*)d_out;

    float *p0 = nullptr, *p1 = nullptr;
    __half2* dr = nullptr;
    cudaGetSymbolAddress((void**)&p0, g_buf0);
    cudaGetSymbolAddress((void**)&p1, g_buf1);
    cudaGetSymbolAddress((void**)&dr, g_dr);
    float* bufs[2] = { p0, p1 };

    cudaLaunchAttribute attrs[1];
    attrs[0].id = cudaLaunchAttributeProgrammaticStreamSerialization;
    attrs[0].val.programmaticStreamSerializationAllowed = 1;

    // Step 0 config (R9 geometry).
    cudaLaunchConfig_t cfg0 = {};
    cfg0.gridDim = dim3(W / 8, W / 4, BATCH);     // (16, 32, 2)
    cfg0.blockDim = dim3(32, 4, 4);
    cfg0.stream = 0;
    cfg0.attrs = attrs;
    cfg0.numAttrs = 1;

    // Steps 1..39 config (y=8, z=16 tiles; one full wave of 256 CTAs).
    cudaLaunchConfig_t cfg = cfg0;
    cfg.gridDim = dim3(W / 16, W / 8, BATCH);     // (8, 16, 2) = 256 blocks
    cfg.blockDim = dim3(32, 8, 2);                // 512 threads

    // Step 0: fused fp16 packing + first micro-step.
    cudaLaunchKernelEx(&cfg0, fk_step0, u_t0, bufs[1], D_map, rho_map,
                       (__half2*)dr, dt_days);

    // Steps 1..39 (ping-pong; step s reads bufs[s&1], writes bufs[(s+1)&1]).
    for (int s = 1; s < NSTEPS; ++s) {
        const float* src = bufs[s & 1];
        float*       dst = bufs[(s + 1) & 1];
        cudaLaunchKernelEx(&cfg, fk_step, src, dst, out,
                           (const __half2*)dr, dt_days,
                           s / SUBSTEPS, s % SUBSTEPS);
    }

    // Tail for dt==0 batches (fully overlappable).
    cudaLaunchConfig_t tcfg = cfg0;
    tcfg.gridDim = dim3(1, W / 4, (W / 4) * BATCH);
    tcfg.blockDim = dim3(32, 4, 4);
    cudaLaunchKernelEx(&tcfg, fk_tail, u_t0, out, dt_days);

    (void)in_sizes; (void)n_in; (void)out_size;
}

// round 14
// speedup vs baseline: 1.4308x; 1.4308x over previous
#include <cuda_runtime.h>
#include <cuda_fp16.h>

// Fisher-Kolmogorov rollout. R14: two micro-steps fused per kernel with ONE
// __syncthreads(). Phase 1: CTA computes 10x10 halo'd mid rows into smem
// (51.2KB). Phase 2: outputs from smem mids. fp16 {D,rho}, PDL, pair0 packs dr.

#define W        128
#define BATCH    2
#define SUBSTEPS 10
#define MAX_DAYS 4
#define NPAIRS   (SUBSTEPS * MAX_DAYS / 2)   // 20
#define PPD      (SUBSTEPS / 2)              // 5 pairs per day
#define MICRO_DT 0.1f

#define VOL  ((size_t)W * W * W)
#define NTOT (BATCH * VOL)

#define SMEM_BYTES (10 * 10 * 128 * 4)       // 51200

__device__ float g_buf0[NTOT];
__device__ float g_buf1[NTOT];
__device__ __half2 g_dr[NTOT];               // {D, rho} per point (16 MB)

struct __align__(16) H24 { __half2 h[4]; };

__device__ __forceinline__ float4 f4ld(const float* p) {
    return *reinterpret_cast<const float4*>(p);
}
__device__ __forceinline__ void f4st(float* p, float4 v) {
    *reinterpret_cast<float4*>(p) = v;
}

__device__ __forceinline__ void fk_comp(float& o, float c, float nb2,
                                        float nb4, __half2 drh)
{
    const float2 d2 = __half22float2(drh);    // x=D, y=rho
    const float lap = nb2 + nb4 - 6.0f * c;
    o = c + MICRO_DT * (d2.x * lap + d2.y * c * (1.0f - c));
}

__device__ __forceinline__ float4 fk_point(float4 c, float4 ym, float4 yp,
                                           float4 zm, float4 zp,
                                           float lf, float rt, H24 q)
{
    float4 o;
    fk_comp(o.x, c.x, lf  + c.y, ym.x + yp.x + zm.x + zp.x, q.h[0]);
    fk_comp(o.y, c.y, c.x + c.z, ym.y + yp.y + zm.y + zp.y, q.h[1]);
    fk_comp(o.z, c.z, c.y + c.w, ym.z + yp.z + zm.z + zp.z, q.h[2]);
    fk_comp(o.w, c.w, c.z + rt,  ym.w + yp.w + zm.w + zp.w, q.h[3]);
    return o;
}

__device__ __forceinline__ float4 clip01(float4 v)
{
    v.x = fminf(fmaxf(v.x, 0.f), 1.f);
    v.y = fminf(fmaxf(v.y, 0.f), 1.f);
    v.z = fminf(fmaxf(v.z, 0.f), 1.f);
    v.w = fminf(fmaxf(v.w, 0.f), 1.f);
    return v;
}

__device__ __forceinline__ H24 pack_dr(float4 d, float4 r)
{
    H24 q;
    q.h[0] = __floats2half2_rn(d.x, r.x);
    q.h[1] = __floats2half2_rn(d.y, r.y);
    q.h[2] = __floats2half2_rn(d.z, r.z);
    q.h[3] = __floats2half2_rn(d.w, r.w);
    return q;
}

__device__ __forceinline__ void xhalo(float4 u, int tx, float& lf, float& rt)
{
    lf = __shfl_up_sync(0xffffffffu, u.w, 1);
    rt = __shfl_down_sync(0xffffffffu, u.x, 1);
    if (tx == 0)  lf = 0.f;
    if (tx == 31) rt = 0.f;
}

// Phase-2 helper shared by both pair kernels. Reads mids from smem, dr packed.
__device__ __forceinline__ void pair_phase2(
    const float* __restrict__ smid,
    float* __restrict__ udst, float* __restrict__ uout,
    const __half2* __restrict__ dr,
    size_t bb, int y0, int zb, int tx, int ty, int tz, int x4, bool fin)
{
    const size_t PL = (size_t)W * W;
    const int y = y0 + ty;
    const int r_s = ty + 1;
    #pragma unroll
    for (int dz = 0; dz < 4; ++dz) {
        const int p_s = tz * 4 + dz + 1;
        const int z   = zb + tz * 4 + dz;
        const float* pc = smid + (p_s * 10 + r_s) * 128;
        const float4 c  = f4ld(pc + x4);
        const float4 ym = f4ld(smid + (p_s * 10 + r_s - 1) * 128 + x4);
        const float4 yp = f4ld(smid + (p_s * 10 + r_s + 1) * 128 + x4);
        const float4 zm = f4ld(smid + ((p_s - 1) * 10 + r_s) * 128 + x4);
        const float4 zp = f4ld(smid + ((p_s + 1) * 10 + r_s) * 128 + x4);

        const size_t g = bb + ((size_t)z * W + y) * W + x4;
        const H24 q = *reinterpret_cast<const H24*>(dr + g);

        float lf, rt;
        xhalo(c, tx, lf, rt);
        float4 o = fk_point(c, ym, yp, zm, zp, lf, rt, q);

        if (fin) *reinterpret_cast<float4*>(uout + g) = clip01(o);
        else     *reinterpret_cast<float4*>(udst + g) = o;
    }
}

// ---- pairs 1..19: fp32 state, packed dr ----
__global__ __launch_bounds__(512, 2)
void fk_pair(const float* __restrict__ usrc,
             float* __restrict__ udst,
             float* __restrict__ uout,
             const __half2* __restrict__ dr,
             const int* __restrict__ dt_days,
             int pair)
{
#if __CUDA_ARCH__ >= 900
    cudaTriggerProgrammaticLaunchCompletion();
#endif
    const int b  = blockIdx.z;
    const int dt = __ldg(dt_days + b);
    if (pair >= PPD * dt) return;               // CTA-uniform: all threads exit
    const bool fin = (pair == PPD * dt - 1);

    const int tx = threadIdx.x, ty = threadIdx.y, tz = threadIdx.z;
    const int y0 = blockIdx.y * 8;
    const int zb = blockIdx.x * 8;
    const int x4 = tx << 2;
    const size_t PL = (size_t)W * W;
    const size_t bb = (size_t)b * VOL;

    extern __shared__ float smid[];             // [10 planes][10 rows][128]

#if __CUDA_ARCH__ >= 900
    cudaGridDependencySynchronize();
#endif

    const float4 zero4 = make_float4(0.f, 0.f, 0.f, 0.f);

    // Phase 1: 16 warp-rows compute 100 mid rows (10y x 10z) into smem.
    const int tid16 = tz * 8 + ty;
    for (int idx = tid16; idx < 100; idx += 16) {
        const int p = idx / 10;                 // plane zb-1+p
        const int r = idx - p * 10;             // row   y0-1+r
        const int gy = y0 - 1 + r;
        const int gz = zb - 1 + p;
        float4 m = zero4;
        if ((unsigned)gy < W && (unsigned)gz < W) {
            const size_t bm = bb + ((size_t)gz * W + gy) * W + x4;
            const float4 c   = f4ld(usrc + bm);
            const float4 ymv = (gy > 0)     ? f4ld(usrc + bm - W)  : zero4;
            const float4 ypv = (gy < W - 1) ? f4ld(usrc + bm + W)  : zero4;
            const float4 zmv = (gz > 0)     ? f4ld(usrc + bm - PL) : zero4;
            const float4 zpv = (gz < W - 1) ? f4ld(usrc + bm + PL) : zero4;
            const H24 q = *reinterpret_cast<const H24*>(dr + bm);
            float lf, rt;
            xhalo(c, tx, lf, rt);
            m = fk_point(c, ymv, ypv, zmv, zpv, lf, rt, q);
        }
        f4st(smid + (p * 10 + r) * 128 + x4, m);
    }

    __syncthreads();                             // the ONLY barrier

    pair_phase2(smid, udst, uout, dr, bb, y0, zb, tx, ty, tz, x4, fin);
}

// ---- pair 0: reads fp32 u_t0 + D/rho, packs g_dr in phase 1 ----
__global__ __launch_bounds__(512, 2)
void fk_pair0(const float* __restrict__ usrc,
              float* __restrict__ udst,
              const float* __restrict__ Dm,
              const float* __restrict__ Rm,
              __half2* __restrict__ dr,
              const int* __restrict__ dt_days)
{
#if __CUDA_ARCH__ >= 900
    cudaTriggerProgrammaticLaunchCompletion();
#endif
    const int b  = blockIdx.z;
    const int dt = __ldg(dt_days + b);
    if (dt <= 0) return;                         // pair 0 active iff dt>=1
    // fin would need 5*dt == 1: impossible -> pair 0 never writes d_out.

    const int tx = threadIdx.x, ty = threadIdx.y, tz = threadIdx.z;
    const int y0 = blockIdx.y * 8;
    const int zb = blockIdx.x * 8;
    const int x4 = tx << 2;
    const size_t PL = (size_t)W * W;
    const size_t bb = (size_t)b * VOL;

    extern __shared__ float smid[];

    const float4 zero4 = make_float4(0.f, 0.f, 0.f, 0.f);

    const int tid16 = tz * 8 + ty;
    for (int idx = tid16; idx < 100; idx += 16) {
        const int p = idx / 10;
        const int r = idx - p * 10;
        const int gy = y0 - 1 + r;
        const int gz = zb - 1 + p;
        float4 m = zero4;
        if ((unsigned)gy < W && (unsigned)gz < W) {
            const size_t bm = bb + ((size_t)gz * W + gy) * W + x4;
            const float4 c   = f4ld(usrc + bm);
            const float4 ymv = (gy > 0)     ? f4ld(usrc + bm - W)  : zero4;
            const float4 ypv = (gy < W - 1) ? f4ld(usrc + bm + W)  : zero4;
            const float4 zmv = (gz > 0)     ? f4ld(usrc + bm - PL) : zero4;
            const float4 zpv = (gz < W - 1) ? f4ld(usrc + bm + PL) : zero4;
            const float4 dv  = f4ld(Dm + bm);
            const float4 rv  = f4ld(Rm + bm);
            const H24 q = pack_dr(dv, rv);
            *reinterpret_cast<H24*>(dr + bm) = q;   // footprint covers outputs
            float lf, rt;
            xhalo(c, tx, lf, rt);
            m = fk_point(c, ymv, ypv, zmv, zpv, lf, rt, q);
        }
        f4st(smid + (p * 10 + r) * 128 + x4, m);
    }

    __syncthreads();    // orders smem mids AND this CTA's g_dr writes (CTA scope)

    pair_phase2(smid, udst, nullptr, (const __half2*)dr,
                bb, y0, zb, tx, ty, tz, x4, false);
}

// dt==0 batches: clipped copy of u_t0 -> d_out (independent; no gridsync).
__global__ __launch_bounds__(512)
void fk_tail(const float* __restrict__ u0,
             float* __restrict__ out,
             const int* __restrict__ dt_days)
{
#if __CUDA_ARCH__ >= 900
    cudaTriggerProgrammaticLaunchCompletion();
#endif
    const int b = blockIdx.z >> 5;
    if (__ldg(dt_days + b) != 0) return;

    const int x4 = threadIdx.x << 2;
    const int y  = blockIdx.y * 4 + threadIdx.y;
    const int z  = (blockIdx.z & 31) * 4 + threadIdx.z;
    const size_t base = (((size_t)b * W + z) * W + y) * W + x4;

    float4 v = f4ld(u0 + base);
    *reinterpret_cast<float4*>(out + base) = clip01(v);
}

extern "C" void kernel_launch(void* const* d_in, const int* in_sizes, int n_in,
                              void* d_out, int out_size)
{
    const float* u_t0    = (const float*)d_in[0];
    const float* D_map   = (const float*)d_in[1];
    const float* rho_map = (const float*)d_in[2];
    const int*   dt_days = (const int*)  d_in[3];
    float*       out     = (float*)d_out;

    float *p0 = nullptr, *p1 = nullptr;
    __half2* dr = nullptr;
    cudaGetSymbolAddress((void**)&p0, g_buf0);
    cudaGetSymbolAddress((void**)&p1, g_buf1);
    cudaGetSymbolAddress((void**)&dr, g_dr);
    float* bufs[2] = { p0, p1 };

    cudaFuncSetAttribute(fk_pair,  cudaFuncAttributeMaxDynamicSharedMemorySize,
                         SMEM_BYTES);
    cudaFuncSetAttribute(fk_pair0, cudaFuncAttributeMaxDynamicSharedMemorySize,
                         SMEM_BYTES);

    cudaLaunchAttribute attrs[1];
    attrs[0].id = cudaLaunchAttributeProgrammaticStreamSerialization;
    attrs[0].val.programmaticStreamSerializationAllowed = 1;

    cudaLaunchConfig_t cfg = {};
    cfg.gridDim = dim3(W / 8, W / 8, BATCH);     // (16, 16, 2) = 512 CTAs
    cfg.blockDim = dim3(32, 8, 2);               // 512 threads
    cfg.dynamicSmemBytes = SMEM_BYTES;
    cfg.stream = 0;
    cfg.attrs = attrs;
    cfg.numAttrs = 1;

    // Pair 0: fused dr packing + micro-steps 0,1.  Writes bufs[0].
    cudaLaunchKernelEx(&cfg, fk_pair0, u_t0, bufs[0], D_map, rho_map,
                       (__half2*)dr, dt_days);

    // Pairs 1..19: reads bufs[(p+1)&1], writes bufs[p&1].
    for (int p = 1; p < NPAIRS; ++p) {
        const float* src = bufs[(p + 1) & 1];
        float*       dst = bufs[p & 1];
        cudaLaunchKernelEx(&cfg, fk_pair, src, dst, out,
                           (const __half2*)dr, dt_days, p);
    }

    // Tail for dt==0 batches (fully overlappable).
    cudaLaunchConfig_t tcfg = cfg;
    tcfg.gridDim = dim3(1, W / 4, (W / 4) * BATCH);
    tcfg.blockDim = dim3(32, 4, 4);
    tcfg.dynamicSmemBytes = 0;
    cudaLaunchKernelEx(&tcfg, fk_tail, u_t0, out, dt_days);

    (void)in_sizes; (void)n_in; (void)out_size;
}

// round 15
// speedup vs baseline: 1.4751x; 1.0310x over previous
#include <cuda_runtime.h>
#include <cuda_fp16.h>

// Fisher-Kolmogorov rollout. R15 = R14 (one-barrier fused step-pair) + dr
// staged in smem: phase 1 computes 10x10 mid rows AND stashes interior dr;
// phase 2 is pure smem + stores. fp16 {D,rho}, PDL, pair0 packs dr.

#define W        128
#define BATCH    2
#define SUBSTEPS 10
#define MAX_DAYS 4
#define NPAIRS   (SUBSTEPS * MAX_DAYS / 2)   // 20
#define PPD      (SUBSTEPS / 2)              // 5 pairs per day
#define MICRO_DT 0.1f

#define VOL  ((size_t)W * W * W)
#define NTOT (BATCH * VOL)

// smem: mids 100 rows x 512B = 51200 B, then dr 64 rows x 512B = 32768 B
#define SM_MID_FLOATS (100 * 128)
#define SMEM_BYTES    ((100 + 64) * 128 * 4)   // 83968

__device__ float g_buf0[NTOT];
__device__ float g_buf1[NTOT];
__device__ __half2 g_dr[NTOT];               // {D, rho} per point (16 MB)

struct __align__(16) H24 { __half2 h[4]; };

__device__ __forceinline__ float4 f4ld(const float* p) {
    return *reinterpret_cast<const float4*>(p);
}
__device__ __forceinline__ void f4st(float* p, float4 v) {
    *reinterpret_cast<float4*>(p) = v;
}

__device__ __forceinline__ void fk_comp(float& o, float c, float nb2,
                                        float nb4, __half2 drh)
{
    const float2 d2 = __half22float2(drh);    // x=D, y=rho
    const float lap = nb2 + nb4 - 6.0f * c;
    o = c + MICRO_DT * (d2.x * lap + d2.y * c * (1.0f - c));
}

__device__ __forceinline__ float4 fk_point(float4 c, float4 ym, float4 yp,
                                           float4 zm, float4 zp,
                                           float lf, float rt, H24 q)
{
    float4 o;
    fk_comp(o.x, c.x, lf  + c.y, ym.x + yp.x + zm.x + zp.x, q.h[0]);
    fk_comp(o.y, c.y, c.x + c.z, ym.y + yp.y + zm.y + zp.y, q.h[1]);
    fk_comp(o.z, c.z, c.y + c.w, ym.z + yp.z + zm.z + zp.z, q.h[2]);
    fk_comp(o.w, c.w, c.z + rt,  ym.w + yp.w + zm.w + zp.w, q.h[3]);
    return o;
}

__device__ __forceinline__ float4 clip01(float4 v)
{
    v.x = fminf(fmaxf(v.x, 0.f), 1.f);
    v.y = fminf(fmaxf(v.y, 0.f), 1.f);
    v.z = fminf(fmaxf(v.z, 0.f), 1.f);
    v.w = fminf(fmaxf(v.w, 0.f), 1.f);
    return v;
}

__device__ __forceinline__ H24 pack_dr(float4 d, float4 r)
{
    H24 q;
    q.h[0] = __floats2half2_rn(d.x, r.x);
    q.h[1] = __floats2half2_rn(d.y, r.y);
    q.h[2] = __floats2half2_rn(d.z, r.z);
    q.h[3] = __floats2half2_rn(d.w, r.w);
    return q;
}

__device__ __forceinline__ void xhalo(float4 u, int tx, float& lf, float& rt)
{
    lf = __shfl_up_sync(0xffffffffu, u.w, 1);
    rt = __shfl_down_sync(0xffffffffu, u.x, 1);
    if (tx == 0)  lf = 0.f;
    if (tx == 31) rt = 0.f;
}

// Phase 2: pure smem reads (mids + dr) -> gmem stores.
__device__ __forceinline__ void pair_phase2(
    const float* __restrict__ smid,
    float* __restrict__ udst, float* __restrict__ uout,
    size_t bb, int y0, int zb, int tx, int ty, int tz, int x4, bool fin)
{
    const float* sdr = smid + SM_MID_FLOATS;
    const int y = y0 + ty;
    const int r_s = ty + 1;
    #pragma unroll
    for (int dz = 0; dz < 4; ++dz) {
        const int zo  = tz * 4 + dz;              // 0..7 local
        const int p_s = zo + 1;
        const int z   = zb + zo;
        const float* pc = smid + (p_s * 10 + r_s) * 128;
        const float4 c  = f4ld(pc + x4);
        const float4 ym = f4ld(smid + (p_s * 10 + r_s - 1) * 128 + x4);
        const float4 yp = f4ld(smid + (p_s * 10 + r_s + 1) * 128 + x4);
        const float4 zm = f4ld(smid + ((p_s - 1) * 10 + r_s) * 128 + x4);
        const float4 zp = f4ld(smid + ((p_s + 1) * 10 + r_s) * 128 + x4);
        const H24 q = *reinterpret_cast<const H24*>(sdr + (zo * 8 + ty) * 128 + x4);

        float lf, rt;
        xhalo(c, tx, lf, rt);
        float4 o = fk_point(c, ym, yp, zm, zp, lf, rt, q);

        const size_t g = bb + ((size_t)z * W + y) * W + x4;
        if (fin) *reinterpret_cast<float4*>(uout + g) = clip01(o);
        else     *reinterpret_cast<float4*>(udst + g) = o;
    }
}

// ---- pairs 1..19: fp32 state, packed dr from gmem ----
__global__ __launch_bounds__(512, 2)
void fk_pair(const float* __restrict__ usrc,
             float* __restrict__ udst,
             float* __restrict__ uout,
             const __half2* __restrict__ dr,
             const int* __restrict__ dt_days,
             int pair)
{
#if __CUDA_ARCH__ >= 900
    cudaTriggerProgrammaticLaunchCompletion();
#endif
    const int b  = blockIdx.z;
    const int dt = __ldg(dt_days + b);
    if (pair >= PPD * dt) return;               // CTA-uniform early exit
    const bool fin = (pair == PPD * dt - 1);

    const int tx = threadIdx.x, ty = threadIdx.y, tz = threadIdx.z;
    const int y0 = blockIdx.y * 8;
    const int zb = blockIdx.x * 8;
    const int x4 = tx << 2;
    const size_t PL = (size_t)W * W;
    const size_t bb = (size_t)b * VOL;

    extern __shared__ float smid[];             // mids [10p][10r][128] + dr

#if __CUDA_ARCH__ >= 900
    cudaGridDependencySynchronize();
#endif

    const float4 zero4 = make_float4(0.f, 0.f, 0.f, 0.f);
    float* sdr = smid + SM_MID_FLOATS;

    // Phase 1: 16 row-groups compute 100 mid rows; stash interior dr.
    const int tid16 = tz * 8 + ty;
    for (int idx = tid16; idx < 100; idx += 16) {
        const int p = idx / 10;                 // plane zb-1+p
        const int r = idx - p * 10;             // row   y0-1+r
        const int gy = y0 - 1 + r;
        const int gz = zb - 1 + p;
        float4 m = zero4;
        if ((unsigned)gy < W && (unsigned)gz < W) {
            const size_t bm = bb + ((size_t)gz * W + gy) * W + x4;
            const float4 c   = f4ld(usrc + bm);
            const float4 ymv = (gy > 0)     ? f4ld(usrc + bm - W)  : zero4;
            const float4 ypv = (gy < W - 1) ? f4ld(usrc + bm + W)  : zero4;
            const float4 zmv = (gz > 0)     ? f4ld(usrc + bm - PL) : zero4;
            const float4 zpv = (gz < W - 1) ? f4ld(usrc + bm + PL) : zero4;
            const H24 q = *reinterpret_cast<const H24*>(dr + bm);
            if (((unsigned)(p - 1) < 8u) && ((unsigned)(r - 1) < 8u))
                *reinterpret_cast<H24*>(sdr + ((p - 1) * 8 + (r - 1)) * 128 + x4) = q;
            float lf, rt;
            xhalo(c, tx, lf, rt);
            m = fk_point(c, ymv, ypv, zmv, zpv, lf, rt, q);
        }
        f4st(smid + (p * 10 + r) * 128 + x4, m);
    }

    __syncthreads();                             // the ONLY barrier

    pair_phase2(smid, udst, uout, bb, y0, zb, tx, ty, tz, x4, fin);
}

// ---- pair 0: reads fp32 u_t0 + D/rho, packs g_dr in phase 1 ----
__global__ __launch_bounds__(512, 2)
void fk_pair0(const float* __restrict__ usrc,
              float* __restrict__ udst,
              const float* __restrict__ Dm,
              const float* __restrict__ Rm,
              __half2* __restrict__ dr,
              const int* __restrict__ dt_days)
{
#if __CUDA_ARCH__ >= 900
    cudaTriggerProgrammaticLaunchCompletion();
#endif
    const int b  = blockIdx.z;
    const int dt = __ldg(dt_days + b);
    if (dt <= 0) return;                         // pair 0 active iff dt>=1
    // fin would need 5*dt == 1: impossible -> pair 0 never writes d_out.

    const int tx = threadIdx.x, ty = threadIdx.y, tz = threadIdx.z;
    const int y0 = blockIdx.y * 8;
    const int zb = blockIdx.x * 8;
    const int x4 = tx << 2;
    const size_t PL = (size_t)W * W;
    const size_t bb = (size_t)b * VOL;

    extern __shared__ float smid[];
    float* sdr = smid + SM_MID_FLOATS;

    const float4 zero4 = make_float4(0.f, 0.f, 0.f, 0.f);

    const int tid16 = tz * 8 + ty;
    for (int idx = tid16; idx < 100; idx += 16) {
        const int p = idx / 10;
        const int r = idx - p * 10;
        const int gy = y0 - 1 + r;
        const int gz = zb - 1 + p;
        float4 m = zero4;
        if ((unsigned)gy < W && (unsigned)gz < W) {
            const size_t bm = bb + ((size_t)gz * W + gy) * W + x4;
            const float4 c   = f4ld(usrc + bm);
            const float4 ymv = (gy > 0)     ? f4ld(usrc + bm - W)  : zero4;
            const float4 ypv = (gy < W - 1) ? f4ld(usrc + bm + W)  : zero4;
            const float4 zmv = (gz > 0)     ? f4ld(usrc + bm - PL) : zero4;
            const float4 zpv = (gz < W - 1) ? f4ld(usrc + bm + PL) : zero4;
            const float4 dv  = f4ld(Dm + bm);
            const float4 rv  = f4ld(Rm + bm);
            const H24 q = pack_dr(dv, rv);
            *reinterpret_cast<H24*>(dr + bm) = q;   // persist for later pairs
            if (((unsigned)(p - 1) < 8u) && ((unsigned)(r - 1) < 8u))
                *reinterpret_cast<H24*>(sdr + ((p - 1) * 8 + (r - 1)) * 128 + x4) = q;
            float lf, rt;
            xhalo(c, tx, lf, rt);
            m = fk_point(c, ymv, ypv, zmv, zpv, lf, rt, q);
        }
        f4st(smid + (p * 10 + r) * 128 + x4, m);
    }

    __syncthreads();

    pair_phase2(smid, udst, nullptr, bb, y0, zb, tx, ty, tz, x4, false);
}

// dt==0 batches: clipped copy of u_t0 -> d_out (independent; no gridsync).
__global__ __launch_bounds__(512)
void fk_tail(const float* __restrict__ u0,
             float* __restrict__ out,
             const int* __restrict__ dt_days)
{
#if __CUDA_ARCH__ >= 900
    cudaTriggerProgrammaticLaunchCompletion();
#endif
    const int b = blockIdx.z >> 5;
    if (__ldg(dt_days + b) != 0) return;

    const int x4 = threadIdx.x << 2;
    const int y  = blockIdx.y * 4 + threadIdx.y;
    const int z  = (blockIdx.z & 31) * 4 + threadIdx.z;
    const size_t base = (((size_t)b * W + z) * W + y) * W + x4;

    float4 v = f4ld(u0 + base);
    *reinterpret_cast<float4*>(out + base) = clip01(v);
}

extern "C" void kernel_launch(void* const* d_in, const int* in_sizes, int n_in,
                              void* d_out, int out_size)
{
    const float* u_t0    = (const float*)d_in[0];
    const float* D_map   = (const float*)d_in[1];
    const float* rho_map = (const float*)d_in[2];
    const int*   dt_days = (const int*)  d_in[3];
    float*       out     = (float*)d_out;

    float *p0 = nullptr, *p1 = nullptr;
    __half2* dr = nullptr;
    cudaGetSymbolAddress((void**)&p0, g_buf0);
    cudaGetSymbolAddress((void**)&p1, g_buf1);
    cudaGetSymbolAddress((void**)&dr, g_dr);
    float* bufs[2] = { p0, p1 };

    cudaFuncSetAttribute(fk_pair,  cudaFuncAttributeMaxDynamicSharedMemorySize,
                         SMEM_BYTES);
    cudaFuncSetAttribute(fk_pair0, cudaFuncAttributeMaxDynamicSharedMemorySize,
                         SMEM_BYTES);

    cudaLaunchAttribute attrs[1];
    attrs[0].id = cudaLaunchAttributeProgrammaticStreamSerialization;
    attrs[0].val.programmaticStreamSerializationAllowed = 1;

    cudaLaunchConfig_t cfg = {};
    cfg.gridDim = dim3(W / 8, W / 8, BATCH);     // (16, 16, 2) = 512 CTAs
    cfg.blockDim = dim3(32, 8, 2);               // 512 threads
    cfg.dynamicSmemBytes = SMEM_BYTES;
    cfg.stream = 0;
    cfg.attrs = attrs;
    cfg.numAttrs = 1;

    // Pair 0: fused dr packing + micro-steps 0,1.  Writes bufs[0].
    cudaLaunchKernelEx(&cfg, fk_pair0, u_t0, bufs[0], D_map, rho_map,
                       (__half2*)dr, dt_days);

    // Pairs 1..19: reads bufs[(p+1)&1], writes bufs[p&1].
    for (int p = 1; p < NPAIRS; ++p) {
        const float* src = bufs[(p + 1) & 1];
        float*       dst = bufs[p & 1];
        cudaLaunchKernelEx(&cfg, fk_pair, src, dst, out,
                           (const __half2*)dr, dt_days, p);
    }

    // Tail for dt==0 batches (fully overlappable).
    cudaLaunchConfig_t tcfg = cfg;
    tcfg.gridDim = dim3(1, W / 4, (W / 4) * BATCH);
    tcfg.blockDim = dim3(32, 4, 4);
    tcfg.dynamicSmemBytes = 0;
    cudaLaunchKernelEx(&tcfg, fk_tail, u_t0, out, dt_days);

    (void)in_sizes; (void)n_in; (void)out_size;
}